// round 2
// baseline (speedup 1.0000x reference)
#include <cuda_runtime.h>

#define N_NODES   50000
#define IN_FEAT   128
#define OUT_FEAT  128
#define NUM_RELS  16

// Scratch: hw[r][n][o] = (h @ W[r])[n][o]   (409.6 MB, static device global)
__device__ float g_hw[(size_t)NUM_RELS * N_NODES * OUT_FEAT];

// ---------------------------------------------------------------------------
// Packed f32x2 helpers (sm_100+). ptxas will not auto-fuse FFMA2 from C++.
// ---------------------------------------------------------------------------
__device__ __forceinline__ unsigned long long ffma2(unsigned long long a,
                                                    unsigned long long b,
                                                    unsigned long long c) {
    unsigned long long d;
    asm("fma.rn.f32x2 %0, %1, %2, %3;" : "=l"(d) : "l"(a), "l"(b), "l"(c));
    return d;
}
__device__ __forceinline__ unsigned long long pack2(float lo, float hi) {
    unsigned long long d;
    asm("mov.b64 %0, {%1, %2};" : "=l"(d) : "f"(lo), "f"(hi));
    return d;
}
__device__ __forceinline__ float2 unpack2(unsigned long long v) {
    float2 r;
    asm("mov.b64 {%0, %1}, %2;" : "=f"(r.x), "=f"(r.y) : "l"(v));
    return r;
}

// ---------------------------------------------------------------------------
// Phase 1: hw[r] = h @ W[r]
// Block = 256 threads, tile 128(M) x 128(N), K streamed in chunks of 16.
// Each thread owns an 8x8 output tile accumulated as 32 packed f32x2 regs.
// ---------------------------------------------------------------------------
__global__ void __launch_bounds__(256, 2)
gemm_hw_kernel(const float* __restrict__ h, const float* __restrict__ w)
{
    __shared__ float As[16][128];   // transposed: As[k][m]
    __shared__ float Bs[16][128];   // Bs[k][n]

    const int r  = blockIdx.y;
    const int m0 = blockIdx.x * 128;
    const float* W = w + (size_t)r * IN_FEAT * OUT_FEAT;
    const int tid = threadIdx.x;
    const int tx = tid & 15;    // column group
    const int ty = tid >> 4;    // row group (8 rows)

    unsigned long long acc[8][4];
#pragma unroll
    for (int i = 0; i < 8; i++)
#pragma unroll
        for (int j = 0; j < 4; j++) acc[i][j] = 0ULL;

    for (int k0 = 0; k0 < IN_FEAT; k0 += 16) {
        // Load A tile (128 rows x 16 k), store transposed into As[k][m]
#pragma unroll
        for (int i = tid; i < 512; i += 256) {
            int row = i >> 2, kq = i & 3;
            float4 v = make_float4(0.f, 0.f, 0.f, 0.f);
            if (m0 + row < N_NODES)
                v = *(const float4*)(h + (size_t)(m0 + row) * IN_FEAT + k0 + kq * 4);
            As[kq * 4 + 0][row] = v.x;
            As[kq * 4 + 1][row] = v.y;
            As[kq * 4 + 2][row] = v.z;
            As[kq * 4 + 3][row] = v.w;
        }
        // Load B tile (16 k x 128 n), already K-major in W
#pragma unroll
        for (int i = tid; i < 512; i += 256) {
            int krow = i >> 5, nq = i & 31;
            *(float4*)&Bs[krow][nq * 4] =
                *(const float4*)(W + (size_t)(k0 + krow) * OUT_FEAT + nq * 4);
        }
        __syncthreads();

#pragma unroll
        for (int k = 0; k < 16; k++) {
            float4 a0 = *(const float4*)&As[k][ty * 8];
            float4 a1 = *(const float4*)&As[k][ty * 8 + 4];
            float4 b0 = *(const float4*)&Bs[k][tx * 4];
            float4 b1 = *(const float4*)&Bs[k][64 + tx * 4];
            unsigned long long bp[4] = {
                pack2(b0.x, b0.y), pack2(b0.z, b0.w),
                pack2(b1.x, b1.y), pack2(b1.z, b1.w)
            };
            float av[8] = {a0.x, a0.y, a0.z, a0.w, a1.x, a1.y, a1.z, a1.w};
#pragma unroll
            for (int i = 0; i < 8; i++) {
                unsigned long long ap = pack2(av[i], av[i]);
#pragma unroll
                for (int j = 0; j < 4; j++)
                    acc[i][j] = ffma2(ap, bp[j], acc[i][j]);
            }
        }
        __syncthreads();
    }

    // Store: rows m0 + ty*8 + i, cols [tx*4, tx*4+4) and [64+tx*4, ...)
    float* base = g_hw + (size_t)r * N_NODES * OUT_FEAT;
#pragma unroll
    for (int i = 0; i < 8; i++) {
        int m = m0 + ty * 8 + i;
        if (m < N_NODES) {
            float* p = base + (size_t)m * OUT_FEAT;
            float2 c0 = unpack2(acc[i][0]), c1 = unpack2(acc[i][1]);
            float2 c2 = unpack2(acc[i][2]), c3 = unpack2(acc[i][3]);
            *(float4*)(p + tx * 4)      = make_float4(c0.x, c0.y, c1.x, c1.y);
            *(float4*)(p + 64 + tx * 4) = make_float4(c2.x, c2.y, c3.x, c3.y);
        }
    }
}

// ---------------------------------------------------------------------------
// Phase 2a: zero the output accumulator (harness poisons d_out to 0xAA)
// ---------------------------------------------------------------------------
__global__ void zero_kernel(float4* __restrict__ out, int n4)
{
    int i = blockIdx.x * blockDim.x + threadIdx.x;
    if (i < n4) out[i] = make_float4(0.f, 0.f, 0.f, 0.f);
}

// ---------------------------------------------------------------------------
// Phase 2b: edge scatter. One warp per edge: lane l loads hw[rel,src,4l..4l+3]
// (512B coalesced row read) and issues ONE vector reduction into out[dst].
// red.global.add.v4.f32 (PTX ISA 8.1, sm_90+) — 1 REDG.128 vs 4 REDG.32.
// ---------------------------------------------------------------------------
__global__ void __launch_bounds__(256)
scatter_kernel(const int* __restrict__ src, const int* __restrict__ dst,
               const int* __restrict__ rel, float* __restrict__ out, int E)
{
    int e = blockIdx.x * 8 + (threadIdx.x >> 5);
    if (e >= E) return;
    int lane = threadIdx.x & 31;

    int s  = __ldg(src + e);
    int d  = __ldg(dst + e);
    int rt = __ldg(rel + e);

    const float4* row =
        (const float4*)(g_hw + ((size_t)rt * N_NODES + s) * OUT_FEAT);
    float4 v = row[lane];

    float* o = out + (size_t)d * OUT_FEAT + lane * 4;
    asm volatile("red.global.add.v4.f32 [%0], {%1, %2, %3, %4};"
                 :: "l"(o), "f"(v.x), "f"(v.y), "f"(v.z), "f"(v.w)
                 : "memory");
}

// ---------------------------------------------------------------------------
// Phase 3: out = relu(out + bias)
// ---------------------------------------------------------------------------
__global__ void finalize_kernel(float* __restrict__ out,
                                const float* __restrict__ bias, int n4)
{
    int i = blockIdx.x * blockDim.x + threadIdx.x;
    if (i >= n4) return;
    float4 v = ((float4*)out)[i];
    float4 b = ((const float4*)bias)[i & 31];   // 128 cols = 32 float4 groups
    v.x = fmaxf(v.x + b.x, 0.f);
    v.y = fmaxf(v.y + b.y, 0.f);
    v.z = fmaxf(v.z + b.z, 0.f);
    v.w = fmaxf(v.w + b.w, 0.f);
    ((float4*)out)[i] = v;
}

// ---------------------------------------------------------------------------
// Launch: inputs per metadata order: h, weight, bias, src, dst, rel_type
// ---------------------------------------------------------------------------
extern "C" void kernel_launch(void* const* d_in, const int* in_sizes, int n_in,
                              void* d_out, int out_size)
{
    const float* h    = (const float*)d_in[0];
    const float* w    = (const float*)d_in[1];
    const float* bias = (const float*)d_in[2];
    const int*   src  = (const int*)d_in[3];
    const int*   dst  = (const int*)d_in[4];
    const int*   rel  = (const int*)d_in[5];
    float*       out  = (float*)d_out;

    const int E  = in_sizes[3];
    const int n4 = out_size / 4;

    dim3 ggrid((N_NODES + 127) / 128, NUM_RELS);
    gemm_hw_kernel<<<ggrid, 256>>>(h, w);

    zero_kernel<<<(n4 + 255) / 256, 256>>>((float4*)out, n4);
    scatter_kernel<<<(E + 7) / 8, 256>>>(src, dst, rel, out, E);
    finalize_kernel<<<(n4 + 255) / 256, 256>>>(out, bias, n4);
}

// round 8
// speedup vs baseline: 1.4299x; 1.4299x over previous
#include <cuda_runtime.h>
#include <cuda_bf16.h>
#include <cstdint>

#define N_NODES   50000
#define NUM_RELS  16
// IN_FEAT = OUT_FEAT = K = 128 everywhere below.

// ---------------------------------------------------------------------------
// Static device scratch (allocation APIs are forbidden)
// ---------------------------------------------------------------------------
__device__ float         g_hw  [(size_t)NUM_RELS * N_NODES * 128];  // 409.6 MB
__device__ __nv_bfloat16 g_h_hi[(size_t)N_NODES * 128];
__device__ __nv_bfloat16 g_h_lo[(size_t)N_NODES * 128];
__device__ __nv_bfloat16 g_wt_hi[(size_t)NUM_RELS * 128 * 128];     // W^T[r][n][k]
__device__ __nv_bfloat16 g_wt_lo[(size_t)NUM_RELS * 128 * 128];

// ---------------------------------------------------------------------------
// mma.sync m16n8k16 bf16 (row.col), fp32 accum — supported on base sm_103.
// ---------------------------------------------------------------------------
__device__ __forceinline__ void mma16816(float* c, const uint32_t* a,
                                         const uint32_t* b) {
    asm volatile(
        "mma.sync.aligned.m16n8k16.row.col.f32.bf16.bf16.f32 "
        "{%0,%1,%2,%3}, {%4,%5,%6,%7}, {%8,%9}, {%0,%1,%2,%3};"
        : "+f"(c[0]), "+f"(c[1]), "+f"(c[2]), "+f"(c[3])
        : "r"(a[0]), "r"(a[1]), "r"(a[2]), "r"(a[3]), "r"(b[0]), "r"(b[1]));
}

// ---------------------------------------------------------------------------
// Prep 1: split h (fp32) -> h_hi + h_lo (bf16 pair), row-major [n][k]
// ---------------------------------------------------------------------------
__global__ void split_h_kernel(const float* __restrict__ h, int n4)
{
    int i = blockIdx.x * blockDim.x + threadIdx.x;
    if (i >= n4) return;
    float4 v = ((const float4*)h)[i];
    __nv_bfloat16 hx = __float2bfloat16(v.x), hy = __float2bfloat16(v.y);
    __nv_bfloat16 hz = __float2bfloat16(v.z), hw_ = __float2bfloat16(v.w);
    __nv_bfloat16 lx = __float2bfloat16(v.x - __bfloat162float(hx));
    __nv_bfloat16 ly = __float2bfloat16(v.y - __bfloat162float(hy));
    __nv_bfloat16 lz = __float2bfloat16(v.z - __bfloat162float(hz));
    __nv_bfloat16 lw = __float2bfloat16(v.w - __bfloat162float(hw_));
    __nv_bfloat162* phi = (__nv_bfloat162*)(g_h_hi + (size_t)i * 4);
    __nv_bfloat162* plo = (__nv_bfloat162*)(g_h_lo + (size_t)i * 4);
    phi[0] = __nv_bfloat162(hx, hy); phi[1] = __nv_bfloat162(hz, hw_);
    plo[0] = __nv_bfloat162(lx, ly); plo[1] = __nv_bfloat162(lz, lw);
}

// ---------------------------------------------------------------------------
// Prep 2: W[r][k][n] fp32 -> W^T[r][n][k] bf16 hi/lo (262144 elems, tiny)
// ---------------------------------------------------------------------------
__global__ void split_wt_kernel(const float* __restrict__ w)
{
    int idx = blockIdx.x * blockDim.x + threadIdx.x;
    if (idx >= NUM_RELS * 128 * 128) return;
    int r = idx >> 14, rem = idx & 16383;
    int n = rem >> 7, k = rem & 127;
    float v = w[(r << 14) + (k << 7) + n];
    __nv_bfloat16 hi = __float2bfloat16(v);
    __nv_bfloat16 lo = __float2bfloat16(v - __bfloat162float(hi));
    g_wt_hi[idx] = hi;
    g_wt_lo[idx] = lo;
}

// ---------------------------------------------------------------------------
// Phase 1: hw[r] = h @ W[r], bf16-split (3 terms) via mma.sync.
// CTA = 128(M) x 128(N), full K=128 in smem. 256 threads = 8 warps,
// warp tile 32(M) x 64(N): warps (wm 0..3) x (wn 0..1).
// smem rows padded: 128 + 8 bf16 = 136 elems (272 B) per row.
// ---------------------------------------------------------------------------
#define LDT       136
#define TILE_B    (128 * LDT * 2)          // 34816 bytes per tile
#define SM_A_HI   0
#define SM_A_LO   (TILE_B)
#define SM_B_HI   (TILE_B * 2)
#define SM_B_LO   (TILE_B * 3)
#define SMEM_BYTES (TILE_B * 4)            // 139264

__global__ void __launch_bounds__(256, 1)
gemm_mma_kernel()
{
    extern __shared__ char smem[];
    const int tid  = threadIdx.x;
    const int wid  = tid >> 5;
    const int lane = tid & 31;
    const int wm   = wid & 3;       // 0..3  (32-row slab)
    const int wn   = wid >> 2;      // 0..1  (64-col slab)
    const int r4   = lane >> 2;     // 0..7
    const int c2   = (lane & 3) * 2;

    const int r  = blockIdx.y;
    const int m0 = blockIdx.x * 128;

    const __nv_bfloat16* Ahi = g_h_hi + (size_t)m0 * 128;
    const __nv_bfloat16* Alo = g_h_lo + (size_t)m0 * 128;
    const __nv_bfloat16* Bhi = g_wt_hi + (size_t)r * 16384;
    const __nv_bfloat16* Blo = g_wt_lo + (size_t)r * 16384;

    // ---- fill smem tiles (uint4 = 8 bf16 chunks; 2048 chunks per tile) ----
    const uint4 zero4 = make_uint4(0, 0, 0, 0);
#pragma unroll
    for (int it = 0; it < 8; it++) {
        int idx = it * 256 + tid;
        int row = idx >> 4, k8 = idx & 15;
        uint32_t so = (uint32_t)row * (LDT * 2) + (uint32_t)k8 * 16;
        size_t g = (size_t)row * 128 + k8 * 8;
        bool va = (m0 + row) < N_NODES;
        uint4 vAh = va ? *(const uint4*)(Ahi + g) : zero4;
        uint4 vAl = va ? *(const uint4*)(Alo + g) : zero4;
        *(uint4*)(smem + SM_A_HI + so) = vAh;
        *(uint4*)(smem + SM_A_LO + so) = vAl;
        *(uint4*)(smem + SM_B_HI + so) = *(const uint4*)(Bhi + g);
        *(uint4*)(smem + SM_B_LO + so) = *(const uint4*)(Blo + g);
    }
    __syncthreads();

    float acc[2][8][4];
#pragma unroll
    for (int im = 0; im < 2; im++)
#pragma unroll
        for (int jn = 0; jn < 8; jn++)
#pragma unroll
            for (int q = 0; q < 4; q++) acc[im][jn][q] = 0.f;

    // ---- main loop: 8 K-steps of 16; fused 3-term MMA ----
#pragma unroll
    for (int ks = 0; ks < 8; ks++) {
        const int k0 = ks * 16;
        uint32_t ah[2][4], al[2][4], bh[8][2], bl[8][2];

#pragma unroll
        for (int im = 0; im < 2; im++) {
            int mr = wm * 32 + im * 16 + r4;          // row within tile
            uint32_t o00 = (uint32_t)mr * (LDT * 2) + (k0 + c2) * 2;
            uint32_t o10 = o00 + 8 * (LDT * 2);       // row +8
            ah[im][0] = *(const uint32_t*)(smem + SM_A_HI + o00);
            ah[im][1] = *(const uint32_t*)(smem + SM_A_HI + o10);
            ah[im][2] = *(const uint32_t*)(smem + SM_A_HI + o00 + 16);
            ah[im][3] = *(const uint32_t*)(smem + SM_A_HI + o10 + 16);
            al[im][0] = *(const uint32_t*)(smem + SM_A_LO + o00);
            al[im][1] = *(const uint32_t*)(smem + SM_A_LO + o10);
            al[im][2] = *(const uint32_t*)(smem + SM_A_LO + o00 + 16);
            al[im][3] = *(const uint32_t*)(smem + SM_A_LO + o10 + 16);
        }
#pragma unroll
        for (int jn = 0; jn < 8; jn++) {
            int nr = wn * 64 + jn * 8 + r4;           // B row = n index
            uint32_t o = (uint32_t)nr * (LDT * 2) + (k0 + c2) * 2;
            bh[jn][0] = *(const uint32_t*)(smem + SM_B_HI + o);
            bh[jn][1] = *(const uint32_t*)(smem + SM_B_HI + o + 16);
            bl[jn][0] = *(const uint32_t*)(smem + SM_B_LO + o);
            bl[jn][1] = *(const uint32_t*)(smem + SM_B_LO + o + 16);
        }

#pragma unroll
        for (int im = 0; im < 2; im++)
#pragma unroll
            for (int jn = 0; jn < 8; jn++)
                mma16816(acc[im][jn], ah[im], bh[jn]);
#pragma unroll
        for (int im = 0; im < 2; im++)
#pragma unroll
            for (int jn = 0; jn < 8; jn++)
                mma16816(acc[im][jn], ah[im], bl[jn]);
#pragma unroll
        for (int im = 0; im < 2; im++)
#pragma unroll
            for (int jn = 0; jn < 8; jn++)
                mma16816(acc[im][jn], al[im], bh[jn]);
    }

    // ---- epilogue: write hw rows ----
    float* base = g_hw + (size_t)r * N_NODES * 128;
#pragma unroll
    for (int im = 0; im < 2; im++) {
        int row0 = m0 + wm * 32 + im * 16 + r4;
#pragma unroll
        for (int jn = 0; jn < 8; jn++) {
            int col = wn * 64 + jn * 8 + c2;
            if (row0 < N_NODES)
                *(float2*)(base + (size_t)row0 * 128 + col) =
                    make_float2(acc[im][jn][0], acc[im][jn][1]);
            if (row0 + 8 < N_NODES)
                *(float2*)(base + (size_t)(row0 + 8) * 128 + col) =
                    make_float2(acc[im][jn][2], acc[im][jn][3]);
        }
    }
}

// ---------------------------------------------------------------------------
// Phase 2a: zero output accumulator (harness poisons d_out)
// ---------------------------------------------------------------------------
__global__ void zero_kernel(float4* __restrict__ out, int n4)
{
    int i = blockIdx.x * blockDim.x + threadIdx.x;
    if (i < n4) out[i] = make_float4(0.f, 0.f, 0.f, 0.f);
}

// ---------------------------------------------------------------------------
// Phase 2b: edge scatter. One warp per edge, vector RED (proved in R2).
// ---------------------------------------------------------------------------
__global__ void __launch_bounds__(256)
scatter_kernel(const int* __restrict__ src, const int* __restrict__ dst,
               const int* __restrict__ rel, float* __restrict__ out, int E)
{
    int e = blockIdx.x * 8 + (threadIdx.x >> 5);
    if (e >= E) return;
    int lane = threadIdx.x & 31;

    int s  = __ldg(src + e);
    int d  = __ldg(dst + e);
    int rt = __ldg(rel + e);

    const float4* row =
        (const float4*)(g_hw + ((size_t)rt * N_NODES + s) * 128);
    float4 v = row[lane];

    float* o = out + (size_t)d * 128 + lane * 4;
    asm volatile("red.global.add.v4.f32 [%0], {%1, %2, %3, %4};"
                 :: "l"(o), "f"(v.x), "f"(v.y), "f"(v.z), "f"(v.w)
                 : "memory");
}

// ---------------------------------------------------------------------------
// Phase 3: out = relu(out + bias)
// ---------------------------------------------------------------------------
__global__ void finalize_kernel(float* __restrict__ out,
                                const float* __restrict__ bias, int n4)
{
    int i = blockIdx.x * blockDim.x + threadIdx.x;
    if (i >= n4) return;
    float4 v = ((float4*)out)[i];
    float4 b = ((const float4*)bias)[i & 31];
    v.x = fmaxf(v.x + b.x, 0.f);
    v.y = fmaxf(v.y + b.y, 0.f);
    v.z = fmaxf(v.z + b.z, 0.f);
    v.w = fmaxf(v.w + b.w, 0.f);
    ((float4*)out)[i] = v;
}

// ---------------------------------------------------------------------------
// Launch. Inputs: h, weight, bias, src, dst, rel_type
// cudaFuncSetAttribute is a host-side, non-stream call: executes immediately
// (not captured), deterministic, no static state (per harness rules).
// ---------------------------------------------------------------------------
extern "C" void kernel_launch(void* const* d_in, const int* in_sizes, int n_in,
                              void* d_out, int out_size)
{
    const float* h    = (const float*)d_in[0];
    const float* w    = (const float*)d_in[1];
    const float* bias = (const float*)d_in[2];
    const int*   src  = (const int*)d_in[3];
    const int*   dst  = (const int*)d_in[4];
    const int*   rel  = (const int*)d_in[5];
    float*       out  = (float*)d_out;

    const int E  = in_sizes[3];
    const int n4 = out_size / 4;

    cudaFuncSetAttribute(gemm_mma_kernel,
                         cudaFuncAttributeMaxDynamicSharedMemorySize,
                         SMEM_BYTES);

    split_h_kernel<<<(N_NODES * 128 / 4 + 255) / 256, 256>>>(h, N_NODES * 128 / 4);
    split_wt_kernel<<<(NUM_RELS * 128 * 128 + 255) / 256, 256>>>(w);

    dim3 ggrid((N_NODES + 127) / 128, NUM_RELS);
    gemm_mma_kernel<<<ggrid, 256, SMEM_BYTES>>>();

    zero_kernel<<<(n4 + 255) / 256, 256>>>((float4*)out, n4);
    scatter_kernel<<<(E + 7) / 8, 256>>>(src, dst, rel, out, E);
    finalize_kernel<<<(n4 + 255) / 256, 256>>>(out, bias, n4);
}